// round 5
// baseline (speedup 1.0000x reference)
#include <cuda_runtime.h>

#define Hdim 1024
#define Tlen 2048
#define Bb   2
#define NHh  16
#define HDd  64
#define NTOK (Bb * Tlen)

// Scratch (device globals: no allocation allowed in kernel_launch)
__device__ float g_Q[NTOK * Hdim];    // [B,NH,T,HD]
__device__ float g_K[NTOK * Hdim];    // [B,NH,T,HD]
__device__ float g_V[NTOK * Hdim];    // [B,NH,T,HD]
__device__ float g_ctx[NTOK * Hdim];  // [B*T, H] token-major

// ---------------------------------------------------------------------------
// Projection GEMM: out = (X @ W + bias) * scale
//   X [4096,1024] row-major, W [1024(in),1024(out)] row-major.
// mode 0/1/2 : X = param x, out = g_Q/g_K/g_V with [B,NH,T,HD] permute
//              (mode 0 additionally scales by HD^-0.5)
// mode 3     : X = g_ctx, out = param (plain [4096,1024])
// Tiling: 64x64x16, 256 threads, 4x4 per thread.
// ---------------------------------------------------------------------------
__global__ __launch_bounds__(256) void proj64(const float* __restrict__ Xin,
                                              const float* __restrict__ W,
                                              const float* __restrict__ bias,
                                              float* __restrict__ outp,
                                              int mode)
{
    __shared__ float Xs[16][64];   // [k][m]
    __shared__ float Ws[16][64];   // [k][n]

    const float* X = (mode == 3) ? g_ctx : Xin;
    float* out = (mode == 0) ? g_Q : (mode == 1) ? g_K : (mode == 2) ? g_V : outp;
    const float scale = (mode == 0) ? 0.125f : 1.0f;

    const int tid = threadIdx.x;
    const int tx = tid & 15, ty = tid >> 4;
    const int m0 = blockIdx.y << 6;
    const int n0 = blockIdx.x << 6;

    // loader indices
    const int lrow = tid >> 2;            // 0..63 (m-row of X tile)
    const int lk4  = (tid & 3) << 2;      // 0,4,8,12 (k within tile)
    const int wk   = tid >> 4;            // 0..15 (k-row of W tile)
    const int wn4  = (tid & 15) << 2;     // n within tile

    float acc[4][4];
#pragma unroll
    for (int i = 0; i < 4; i++)
#pragma unroll
        for (int j = 0; j < 4; j++) acc[i][j] = 0.f;

    const float* Xp = X + (m0 + lrow) * Hdim + lk4;
    const float* Wp = W + wk * Hdim + n0 + wn4;

    for (int k0 = 0; k0 < Hdim; k0 += 16) {
        float4 xa = *(const float4*)(Xp + k0);
        Xs[lk4 + 0][lrow] = xa.x;
        Xs[lk4 + 1][lrow] = xa.y;
        Xs[lk4 + 2][lrow] = xa.z;
        Xs[lk4 + 3][lrow] = xa.w;
        *(float4*)&Ws[wk][wn4] = *(const float4*)(Wp + (size_t)k0 * Hdim);
        __syncthreads();
#pragma unroll
        for (int kk = 0; kk < 16; kk++) {
            float a[4], b[4];
            *(float4*)a = *(const float4*)&Xs[kk][ty << 2];
            *(float4*)b = *(const float4*)&Ws[kk][tx << 2];
#pragma unroll
            for (int i = 0; i < 4; i++)
#pragma unroll
                for (int j = 0; j < 4; j++) acc[i][j] += a[i] * b[j];
        }
        __syncthreads();
    }

    const int nbase = n0 + (tx << 2);
    float bb[4];
    *(float4*)bb = *(const float4*)(bias + nbase);

    if (mode == 3) {
#pragma unroll
        for (int i = 0; i < 4; i++) {
            int m = m0 + (ty << 2) + i;
            float4 r = make_float4(acc[i][0] + bb[0], acc[i][1] + bb[1],
                                   acc[i][2] + bb[2], acc[i][3] + bb[3]);
            *(float4*)(out + (size_t)m * Hdim + nbase) = r;
        }
    } else {
        // n tile (64 wide, 64-aligned) spans exactly one head
        const int h = nbase >> 6;
        const int d = nbase & 63;
#pragma unroll
        for (int i = 0; i < 4; i++) {
            int m = m0 + (ty << 2) + i;
            int b = m >> 11;          // /2048
            int t = m & 2047;
            float4 r = make_float4((acc[i][0] + bb[0]) * scale,
                                   (acc[i][1] + bb[1]) * scale,
                                   (acc[i][2] + bb[2]) * scale,
                                   (acc[i][3] + bb[3]) * scale);
            *(float4*)(out + ((((size_t)b * NHh + h) * Tlen + t) * HDd + d)) = r;
        }
    }
}

// ---------------------------------------------------------------------------
// Flash attention: one CTA per (64-query tile, head). Q pre-scaled by HD^-0.5.
// Online softmax over 32 key tiles of 64. 256 threads (16x16), 4x4 microtiles.
// Writes ctx in token-major [B*T, H] layout.
// ---------------------------------------------------------------------------
#define SPITCH 68   // padded row pitch (floats), multiple of 4 for float4

__global__ __launch_bounds__(256, 2) void attn_kernel(const int* __restrict__ mask,
                                                      float* __restrict__ ctx_unused)
{
    extern __shared__ float sm[];
    float* Qs = sm;                         // [d][q]  64 x SPITCH
    float* Ks = Qs + 64 * SPITCH;           // [d][k]
    float* Vs = Ks + 64 * SPITCH;           // [k][d]
    float* Ss = Vs + 64 * SPITCH;           // [q][k] -> then P
    float* rm = Ss + 64 * SPITCH;           // running max [64]
    float* rl = rm + 64;                    // running sum [64]
    float* sc = rl + 64;                    // per-tile rescale [64]
    float* pmax = sc + 64;                  // [4][64]
    float* psum = pmax + 256;               // [4][64]
    int*   mk = (int*)(psum + 256);         // key mask [64]

    const int tid = threadIdx.x;
    const int tx = tid & 15, ty = tid >> 4;
    const int bh = blockIdx.y;
    const int b = bh >> 4, h = bh & 15;
    const int q0 = blockIdx.x << 6;

    const float* Qg = g_Q + ((size_t)bh * Tlen + q0) * HDd;

    // Load Q tile transposed into Qs[d][q]
#pragma unroll
    for (int it = 0; it < 4; it++) {
        int idx = tid + it * 256;           // 0..1023
        int row = idx >> 4;
        int d4 = (idx & 15) << 2;
        float4 v = *(const float4*)(Qg + (size_t)row * HDd + d4);
        Qs[(d4 + 0) * SPITCH + row] = v.x;
        Qs[(d4 + 1) * SPITCH + row] = v.y;
        Qs[(d4 + 2) * SPITCH + row] = v.z;
        Qs[(d4 + 3) * SPITCH + row] = v.w;
    }
    if (tid < 64) { rm[tid] = -1e30f; rl[tid] = 0.f; }

    float o[4][4];
#pragma unroll
    for (int i = 0; i < 4; i++)
#pragma unroll
        for (int j = 0; j < 4; j++) o[i][j] = 0.f;

    const int r = tid & 63;        // softmax row owned by this thread
    const int seg = tid >> 6;      // column segment 0..3
    const int c0 = seg << 4;

    for (int kt = 0; kt < Tlen; kt += 64) {
        const float* Kg = g_K + ((size_t)bh * Tlen + kt) * HDd;
        const float* Vg = g_V + ((size_t)bh * Tlen + kt) * HDd;

        __syncthreads();   // previous tile's PV readers done before overwrite
#pragma unroll
        for (int it = 0; it < 4; it++) {
            int idx = tid + it * 256;
            int row = idx >> 4;
            int d4 = (idx & 15) << 2;
            float4 kv = *(const float4*)(Kg + (size_t)row * HDd + d4);
            Ks[(d4 + 0) * SPITCH + row] = kv.x;
            Ks[(d4 + 1) * SPITCH + row] = kv.y;
            Ks[(d4 + 2) * SPITCH + row] = kv.z;
            Ks[(d4 + 3) * SPITCH + row] = kv.w;
            float4 vv = *(const float4*)(Vg + (size_t)row * HDd + d4);
            *(float4*)(Vs + row * SPITCH + d4) = vv;
        }
        if (tid < 64) mk[tid] = mask[b * Tlen + kt + tid];
        __syncthreads();

        // ---- S = Q K^T (Q pre-scaled) ----
        float s[4][4];
#pragma unroll
        for (int i = 0; i < 4; i++)
#pragma unroll
            for (int j = 0; j < 4; j++) s[i][j] = 0.f;
#pragma unroll 8
        for (int d = 0; d < 64; d++) {
            float a[4], bb4[4];
            *(float4*)a = *(const float4*)(Qs + d * SPITCH + (ty << 2));
            *(float4*)bb4 = *(const float4*)(Ks + d * SPITCH + (tx << 2));
#pragma unroll
            for (int i = 0; i < 4; i++)
#pragma unroll
                for (int j = 0; j < 4; j++) s[i][j] += a[i] * bb4[j];
        }
#pragma unroll
        for (int i = 0; i < 4; i++)
            *(float4*)(Ss + ((ty << 2) + i) * SPITCH + (tx << 2)) =
                make_float4(s[i][0], s[i][1], s[i][2], s[i][3]);
        __syncthreads();

        // ---- online softmax: A) partial max ----
        float mx = -1e30f;
#pragma unroll
        for (int c = 0; c < 16; c++) {
            float sv = Ss[r * SPITCH + c0 + c];
            if (mk[c0 + c]) mx = fmaxf(mx, sv);
        }
        pmax[seg * 64 + r] = mx;
        __syncthreads();

        // ---- B) combine max, rescale factor ----
        if (tid < 64) {
            float mnew = fmaxf(fmaxf(pmax[tid], pmax[64 + tid]),
                               fmaxf(pmax[128 + tid], pmax[192 + tid]));
            mnew = fmaxf(mnew, rm[tid]);
            sc[tid] = __expf(rm[tid] - mnew);
            rm[tid] = mnew;
        }
        __syncthreads();

        // ---- C) exponentiate in place, partial sums ----
        {
            float mn = rm[r];
            float sum = 0.f;
#pragma unroll
            for (int c = 0; c < 16; c++) {
                int cc = c0 + c;
                float p = mk[cc] ? __expf(Ss[r * SPITCH + cc] - mn) : 0.f;
                Ss[r * SPITCH + cc] = p;
                sum += p;
            }
            psum[seg * 64 + r] = sum;
        }
        __syncthreads();

        // ---- D) update running denominator ----
        if (tid < 64)
            rl[tid] = rl[tid] * sc[tid] + psum[tid] + psum[64 + tid] +
                      psum[128 + tid] + psum[192 + tid];

        // ---- rescale accumulator ----
#pragma unroll
        for (int i = 0; i < 4; i++) {
            float f = sc[(ty << 2) + i];
#pragma unroll
            for (int j = 0; j < 4; j++) o[i][j] *= f;
        }

        // ---- O += P V ----
#pragma unroll 4
        for (int kk = 0; kk < 64; kk += 4) {
            float p[4][4], vv[4][4];
#pragma unroll
            for (int i = 0; i < 4; i++)
                *(float4*)p[i] = *(const float4*)(Ss + ((ty << 2) + i) * SPITCH + kk);
#pragma unroll
            for (int l = 0; l < 4; l++)
                *(float4*)vv[l] = *(const float4*)(Vs + (kk + l) * SPITCH + (tx << 2));
#pragma unroll
            for (int i = 0; i < 4; i++)
#pragma unroll
                for (int l = 0; l < 4; l++)
#pragma unroll
                    for (int j = 0; j < 4; j++) o[i][j] += p[i][l] * vv[l][j];
        }
    }
    __syncthreads();   // rl final values visible

    float invl[4];
#pragma unroll
    for (int i = 0; i < 4; i++) invl[i] = 1.f / rl[(ty << 2) + i];

    float* outp = g_ctx + ((size_t)(b * Tlen + q0)) * Hdim + h * HDd + (tx << 2);
#pragma unroll
    for (int i = 0; i < 4; i++) {
        int qq = (ty << 2) + i;
        float4 rv = make_float4(o[i][0] * invl[i], o[i][1] * invl[i],
                                o[i][2] * invl[i], o[i][3] * invl[i]);
        *(float4*)(outp + (size_t)qq * Hdim) = rv;
    }
}

// ---------------------------------------------------------------------------
extern "C" void kernel_launch(void* const* d_in, const int* in_sizes, int n_in,
                              void* d_out, int out_size)
{
    const float* x  = (const float*)d_in[0];
    const int* attn_mask = (const int*)d_in[1];
    const float* Wq = (const float*)d_in[2];
    const float* bq = (const float*)d_in[3];
    const float* Wk = (const float*)d_in[4];
    const float* bk = (const float*)d_in[5];
    const float* Wv = (const float*)d_in[6];
    const float* bv = (const float*)d_in[7];
    const float* Wo = (const float*)d_in[8];
    const float* bo = (const float*)d_in[9];
    float* out = (float*)d_out;

    const int smem_attn = (4 * 64 * SPITCH + 3 * 64 + 2 * 256 + 64) * (int)sizeof(float);
    cudaFuncSetAttribute(attn_kernel, cudaFuncAttributeMaxDynamicSharedMemorySize,
                         smem_attn);

    dim3 gp(Hdim / 64, NTOK / 64);   // (16, 64)
    proj64<<<gp, 256>>>(x, Wq, bq, nullptr, 0);   // Q (scaled)
    proj64<<<gp, 256>>>(x, Wk, bk, nullptr, 1);   // K
    proj64<<<gp, 256>>>(x, Wv, bv, nullptr, 2);   // V

    dim3 ga(Tlen / 64, Bb * NHh);    // (32, 32)
    attn_kernel<<<ga, 256, smem_attn>>>(attn_mask, nullptr);

    proj64<<<gp, 256>>>(nullptr, Wo, bo, out, 3); // output projection
}

// round 16
// speedup vs baseline: 1.4787x; 1.4787x over previous
#include <cuda_runtime.h>
#include <cstdint>

#define Hdim 1024
#define Tlen 2048
#define Bb   2
#define NHh  16
#define HDd  64
#define NTOK (Bb * Tlen)

// Scratch (device globals: no allocation allowed in kernel_launch)
__device__ float g_Q[NTOK * Hdim];    // [B,NH,T,HD]
__device__ float g_K[NTOK * Hdim];    // [B,NH,T,HD]
__device__ float g_V[NTOK * Hdim];    // [B,NH,T,HD]
__device__ float g_ctx[NTOK * Hdim];  // [B*T, H] token-major
__device__ float g_Wt[4 * Hdim * Hdim]; // transposed weights [out][in]

// ===========================================================================
// helpers
// ===========================================================================
__device__ __forceinline__ uint32_t smem_u32(const void* p) {
    uint32_t a;
    asm("{ .reg .u64 t; cvta.to.shared.u64 t, %1; cvt.u32.u64 %0, t; }"
        : "=r"(a) : "l"(p));
    return a;
}
__device__ __forceinline__ void cp_async16(uint32_t saddr, const void* gptr) {
    asm volatile("cp.async.cg.shared.global [%0], [%1], 16;"
                 :: "r"(saddr), "l"(gptr) : "memory");
}
__device__ __forceinline__ uint32_t f2tf32(float f) {
    uint32_t u;
    asm("cvt.rna.tf32.f32 %0, %1;" : "=r"(u) : "f"(f));
    return u;
}
__device__ __forceinline__ void mma_tf32(float* d, const uint32_t* a,
                                         const uint32_t* b) {
    asm volatile(
        "mma.sync.aligned.m16n8k8.row.col.f32.tf32.tf32.f32 "
        "{%0,%1,%2,%3}, {%4,%5,%6,%7}, {%8,%9}, {%0,%1,%2,%3};"
        : "+f"(d[0]), "+f"(d[1]), "+f"(d[2]), "+f"(d[3])
        : "r"(a[0]), "r"(a[1]), "r"(a[2]), "r"(a[3]), "r"(b[0]), "r"(b[1]));
}

// ===========================================================================
// Weight transpose: Wt[n][k] = W[k][n], 1024x1024, 4 matrices
// ===========================================================================
__global__ void transpose4(const float* __restrict__ W0, const float* __restrict__ W1,
                           const float* __restrict__ W2, const float* __restrict__ W3)
{
    __shared__ float t[32][33];
    const float* in = (blockIdx.z == 0) ? W0 : (blockIdx.z == 1) ? W1 :
                      (blockIdx.z == 2) ? W2 : W3;
    float* out = g_Wt + (size_t)blockIdx.z * Hdim * Hdim;
    int x = blockIdx.x * 32 + threadIdx.x;
    int y = blockIdx.y * 32 + threadIdx.y;
#pragma unroll
    for (int i = 0; i < 32; i += 8)
        t[threadIdx.y + i][threadIdx.x] = in[(size_t)(y + i) * Hdim + x];
    __syncthreads();
    x = blockIdx.y * 32 + threadIdx.x;
    y = blockIdx.x * 32 + threadIdx.y;
#pragma unroll
    for (int i = 0; i < 32; i += 8)
        out[(size_t)(y + i) * Hdim + x] = t[threadIdx.x][threadIdx.y + i];
}

// ===========================================================================
// tf32 mma.sync GEMM: C[4096 x 1024] = X @ Wt^T + bias
//   CTA tile 128x128, K chunks of 32, cp.async double buffer, 256 threads.
//   8 warps as 2(m) x 4(n); warp tile 64x32 = 4x4 m16n8k8 atoms.
// mode 0/1/2: X = x param, out = g_Q/g_K/g_V permuted [B,NH,T,HD] (mode 0 *0.125)
// mode 3:     X = g_ctx, out = param (row-major)
// smem pitch 36 floats -> fragment loads provably bank-conflict-free.
// ===========================================================================
#define PITCH 36
#define STGF  (128 * PITCH)            // floats per tile stage
#define SMEM_GEMM (4 * STGF * 4)       // A(2 stages) + B(2 stages), bytes

__global__ __launch_bounds__(256) void gemm_tf32(const float* __restrict__ Xin,
                                                 const float* __restrict__ Wt,
                                                 const float* __restrict__ bias,
                                                 float* __restrict__ outp,
                                                 int mode)
{
    extern __shared__ float smf[];
    const uint32_t sbase = smem_u32(smf);
    const int tid = threadIdx.x;
    const int wid = tid >> 5, lane = tid & 31;

    const float* X = (mode == 3) ? g_ctx : Xin;
    const int m0 = blockIdx.y << 7;
    const int n0 = blockIdx.x << 7;

    const int wm0 = (wid >> 2) << 6;   // warp m offset within tile (0/64)
    const int wn0 = (wid & 3) << 5;    // warp n offset within tile (0/32/64/96)

    // loader mapping: 256 threads x 4 iters cover 128 rows x 8 float4
    const int lrow = tid >> 3;         // 0..31
    const int lc4 = tid & 7;           // 0..7

    float acc[4][4][4];
#pragma unroll
    for (int i = 0; i < 4; i++)
#pragma unroll
        for (int j = 0; j < 4; j++)
#pragma unroll
            for (int e = 0; e < 4; e++) acc[i][j][e] = 0.f;

    const int r4 = lane >> 2, c4 = lane & 3;

    // ---- prefetch chunk 0 ----
    {
        const uint32_t sA = sbase;               // stage 0
        const uint32_t sB = sbase + 2 * STGF * 4;
#pragma unroll
        for (int i = 0; i < 4; i++) {
            int rr = lrow + i * 32;
            uint32_t so = (uint32_t)(rr * PITCH + lc4 * 4) << 2;
            cp_async16(sA + so, X + (size_t)(m0 + rr) * Hdim + lc4 * 4);
            cp_async16(sB + so, Wt + (size_t)(n0 + rr) * Hdim + lc4 * 4);
        }
        asm volatile("cp.async.commit_group;" ::: "memory");
    }

    for (int c = 0; c < Hdim / 32; c++) {
        const int s = c & 1;
        if (c + 1 < Hdim / 32) {
            const int s1 = (c + 1) & 1;
            const int kc = (c + 1) * 32;
            const uint32_t sA = sbase + (uint32_t)(s1 * STGF) * 4;
            const uint32_t sB = sbase + (uint32_t)((2 + s1) * STGF) * 4;
#pragma unroll
            for (int i = 0; i < 4; i++) {
                int rr = lrow + i * 32;
                uint32_t so = (uint32_t)(rr * PITCH + lc4 * 4) << 2;
                cp_async16(sA + so, X + (size_t)(m0 + rr) * Hdim + kc + lc4 * 4);
                cp_async16(sB + so, Wt + (size_t)(n0 + rr) * Hdim + kc + lc4 * 4);
            }
            asm volatile("cp.async.commit_group;" ::: "memory");
            asm volatile("cp.async.wait_group 1;" ::: "memory");
        } else {
            asm volatile("cp.async.wait_group 0;" ::: "memory");
        }
        __syncthreads();

        const float* As = smf + s * STGF;
        const float* Bs = smf + (2 + s) * STGF;

#pragma unroll
        for (int ks = 0; ks < 4; ks++) {
            const int kb = ks * 8;
            uint32_t af[4][4], bf[4][2];
#pragma unroll
            for (int mi = 0; mi < 4; mi++) {
                const float* p = As + (wm0 + mi * 16 + r4) * PITCH + kb + c4;
                af[mi][0] = f2tf32(p[0]);
                af[mi][1] = f2tf32(p[8 * PITCH]);
                af[mi][2] = f2tf32(p[4]);
                af[mi][3] = f2tf32(p[8 * PITCH + 4]);
            }
#pragma unroll
            for (int nj = 0; nj < 4; nj++) {
                const float* p = Bs + (wn0 + nj * 8 + r4) * PITCH + kb + c4;
                bf[nj][0] = f2tf32(p[0]);
                bf[nj][1] = f2tf32(p[4]);
            }
#pragma unroll
            for (int mi = 0; mi < 4; mi++)
#pragma unroll
                for (int nj = 0; nj < 4; nj++)
                    mma_tf32(acc[mi][nj], af[mi], bf[nj]);
        }
        __syncthreads();
    }

    // ---- epilogue ----
    const float scale = (mode == 0) ? 0.125f : 1.0f;
    float* qkv = (mode == 0) ? g_Q : (mode == 1) ? g_K : (mode == 2) ? g_V : outp;
    const int c2 = (lane & 3) << 1;

#pragma unroll
    for (int mi = 0; mi < 4; mi++) {
        const int row0 = m0 + wm0 + mi * 16 + r4;
#pragma unroll
        for (int nj = 0; nj < 4; nj++) {
            const int col = n0 + wn0 + nj * 8 + c2;
            const float b0 = bias[col], b1 = bias[col + 1];
            if (mode == 3) {
                float2 v0 = make_float2(acc[mi][nj][0] + b0, acc[mi][nj][1] + b1);
                float2 v1 = make_float2(acc[mi][nj][2] + b0, acc[mi][nj][3] + b1);
                *(float2*)(qkv + (size_t)row0 * Hdim + col) = v0;
                *(float2*)(qkv + (size_t)(row0 + 8) * Hdim + col) = v1;
            } else {
                const int h = col >> 6, d = col & 63;
                float2 v0 = make_float2((acc[mi][nj][0] + b0) * scale,
                                        (acc[mi][nj][1] + b1) * scale);
                float2 v1 = make_float2((acc[mi][nj][2] + b0) * scale,
                                        (acc[mi][nj][3] + b1) * scale);
                {
                    int m = row0, bq = m >> 11, t = m & 2047;
                    *(float2*)(qkv + ((((size_t)bq * NHh + h) * Tlen + t) * HDd + d)) = v0;
                }
                {
                    int m = row0 + 8, bq = m >> 11, t = m & 2047;
                    *(float2*)(qkv + ((((size_t)bq * NHh + h) * Tlen + t) * HDd + d)) = v1;
                }
            }
        }
    }
}

// ---------------------------------------------------------------------------
// Flash attention (proven R4/R5 fp32 SIMT): one CTA per (64-q tile, head)
// ---------------------------------------------------------------------------
#define SPITCH 68

__global__ __launch_bounds__(256, 2) void attn_kernel(const int* __restrict__ mask,
                                                      float* __restrict__ ctx_unused)
{
    extern __shared__ float sm[];
    float* Qs = sm;
    float* Ks = Qs + 64 * SPITCH;
    float* Vs = Ks + 64 * SPITCH;
    float* Ss = Vs + 64 * SPITCH;
    float* rm = Ss + 64 * SPITCH;
    float* rl = rm + 64;
    float* sc = rl + 64;
    float* pmax = sc + 64;
    float* psum = pmax + 256;
    int*   mk = (int*)(psum + 256);

    const int tid = threadIdx.x;
    const int tx = tid & 15, ty = tid >> 4;
    const int bh = blockIdx.y;
    const int b = bh >> 4, h = bh & 15;
    const int q0 = blockIdx.x << 6;

    const float* Qg = g_Q + ((size_t)bh * Tlen + q0) * HDd;

#pragma unroll
    for (int it = 0; it < 4; it++) {
        int idx = tid + it * 256;
        int row = idx >> 4;
        int d4 = (idx & 15) << 2;
        float4 v = *(const float4*)(Qg + (size_t)row * HDd + d4);
        Qs[(d4 + 0) * SPITCH + row] = v.x;
        Qs[(d4 + 1) * SPITCH + row] = v.y;
        Qs[(d4 + 2) * SPITCH + row] = v.z;
        Qs[(d4 + 3) * SPITCH + row] = v.w;
    }
    if (tid < 64) { rm[tid] = -1e30f; rl[tid] = 0.f; }

    float o[4][4];
#pragma unroll
    for (int i = 0; i < 4; i++)
#pragma unroll
        for (int j = 0; j < 4; j++) o[i][j] = 0.f;

    const int r = tid & 63;
    const int seg = tid >> 6;
    const int c0 = seg << 4;

    for (int kt = 0; kt < Tlen; kt += 64) {
        const float* Kg = g_K + ((size_t)bh * Tlen + kt) * HDd;
        const float* Vg = g_V + ((size_t)bh * Tlen + kt) * HDd;

        __syncthreads();
#pragma unroll
        for (int it = 0; it < 4; it++) {
            int idx = tid + it * 256;
            int row = idx >> 4;
            int d4 = (idx & 15) << 2;
            float4 kv = *(const float4*)(Kg + (size_t)row * HDd + d4);
            Ks[(d4 + 0) * SPITCH + row] = kv.x;
            Ks[(d4 + 1) * SPITCH + row] = kv.y;
            Ks[(d4 + 2) * SPITCH + row] = kv.z;
            Ks[(d4 + 3) * SPITCH + row] = kv.w;
            float4 vv = *(const float4*)(Vg + (size_t)row * HDd + d4);
            *(float4*)(Vs + row * SPITCH + d4) = vv;
        }
        if (tid < 64) mk[tid] = mask[b * Tlen + kt + tid];
        __syncthreads();

        float s[4][4];
#pragma unroll
        for (int i = 0; i < 4; i++)
#pragma unroll
            for (int j = 0; j < 4; j++) s[i][j] = 0.f;
#pragma unroll 8
        for (int d = 0; d < 64; d++) {
            float a[4], bb4[4];
            *(float4*)a = *(const float4*)(Qs + d * SPITCH + (ty << 2));
            *(float4*)bb4 = *(const float4*)(Ks + d * SPITCH + (tx << 2));
#pragma unroll
            for (int i = 0; i < 4; i++)
#pragma unroll
                for (int j = 0; j < 4; j++) s[i][j] += a[i] * bb4[j];
        }
#pragma unroll
        for (int i = 0; i < 4; i++)
            *(float4*)(Ss + ((ty << 2) + i) * SPITCH + (tx << 2)) =
                make_float4(s[i][0], s[i][1], s[i][2], s[i][3]);
        __syncthreads();

        float mx = -1e30f;
#pragma unroll
        for (int c = 0; c < 16; c++) {
            float sv = Ss[r * SPITCH + c0 + c];
            if (mk[c0 + c]) mx = fmaxf(mx, sv);
        }
        pmax[seg * 64 + r] = mx;
        __syncthreads();

        if (tid < 64) {
            float mnew = fmaxf(fmaxf(pmax[tid], pmax[64 + tid]),
                               fmaxf(pmax[128 + tid], pmax[192 + tid]));
            mnew = fmaxf(mnew, rm[tid]);
            sc[tid] = __expf(rm[tid] - mnew);
            rm[tid] = mnew;
        }
        __syncthreads();

        {
            float mn = rm[r];
            float sum = 0.f;
#pragma unroll
            for (int c = 0; c < 16; c++) {
                int cc = c0 + c;
                float p = mk[cc] ? __expf(Ss[r * SPITCH + cc] - mn) : 0.f;
                Ss[r * SPITCH + cc] = p;
                sum += p;
            }
            psum[seg * 64 + r] = sum;
        }
        __syncthreads();

        if (tid < 64)
            rl[tid] = rl[tid] * sc[tid] + psum[tid] + psum[64 + tid] +
                      psum[128 + tid] + psum[192 + tid];

#pragma unroll
        for (int i = 0; i < 4; i++) {
            float f = sc[(ty << 2) + i];
#pragma unroll
            for (int j = 0; j < 4; j++) o[i][j] *= f;
        }

#pragma unroll 4
        for (int kk = 0; kk < 64; kk += 4) {
            float p[4][4], vv[4][4];
#pragma unroll
            for (int i = 0; i < 4; i++)
                *(float4*)p[i] = *(const float4*)(Ss + ((ty << 2) + i) * SPITCH + kk);
#pragma unroll
            for (int l = 0; l < 4; l++)
                *(float4*)vv[l] = *(const float4*)(Vs + (kk + l) * SPITCH + (tx << 2));
#pragma unroll
            for (int i = 0; i < 4; i++)
#pragma unroll
                for (int l = 0; l < 4; l++)
#pragma unroll
                    for (int j = 0; j < 4; j++) o[i][j] += p[i][l] * vv[l][j];
        }
    }
    __syncthreads();

    float invl[4];
#pragma unroll
    for (int i = 0; i < 4; i++) invl[i] = 1.f / rl[(ty << 2) + i];

    float* outp = g_ctx + ((size_t)(b * Tlen + q0)) * Hdim + h * HDd + (tx << 2);
#pragma unroll
    for (int i = 0; i < 4; i++) {
        int qq = (ty << 2) + i;
        float4 rv = make_float4(o[i][0] * invl[i], o[i][1] * invl[i],
                                o[i][2] * invl[i], o[i][3] * invl[i]);
        *(float4*)(outp + (size_t)qq * Hdim) = rv;
    }
}

// ---------------------------------------------------------------------------
extern "C" void kernel_launch(void* const* d_in, const int* in_sizes, int n_in,
                              void* d_out, int out_size)
{
    const float* x  = (const float*)d_in[0];
    const int* attn_mask = (const int*)d_in[1];
    const float* Wq = (const float*)d_in[2];
    const float* bq = (const float*)d_in[3];
    const float* Wk = (const float*)d_in[4];
    const float* bk = (const float*)d_in[5];
    const float* Wv = (const float*)d_in[6];
    const float* bv = (const float*)d_in[7];
    const float* Wo = (const float*)d_in[8];
    const float* bo = (const float*)d_in[9];
    float* out = (float*)d_out;

    const int smem_attn = (4 * 64 * SPITCH + 3 * 64 + 2 * 256 + 64) * (int)sizeof(float);
    cudaFuncSetAttribute(gemm_tf32, cudaFuncAttributeMaxDynamicSharedMemorySize,
                         SMEM_GEMM);
    cudaFuncSetAttribute(attn_kernel, cudaFuncAttributeMaxDynamicSharedMemorySize,
                         smem_attn);

    transpose4<<<dim3(32, 32, 4), dim3(32, 8)>>>(Wq, Wk, Wv, Wo);

    float* wt = nullptr;
    cudaGetSymbolAddress((void**)&wt, g_Wt);

    dim3 gg(Hdim / 128, NTOK / 128);  // (8, 32)
    gemm_tf32<<<gg, 256, SMEM_GEMM>>>(x, wt + 0 * (size_t)Hdim * Hdim, bq, nullptr, 0);
    gemm_tf32<<<gg, 256, SMEM_GEMM>>>(x, wt + 1 * (size_t)Hdim * Hdim, bk, nullptr, 1);
    gemm_tf32<<<gg, 256, SMEM_GEMM>>>(x, wt + 2 * (size_t)Hdim * Hdim, bv, nullptr, 2);

    dim3 ga(Tlen / 64, Bb * NHh);     // (32, 32)
    attn_kernel<<<ga, 256, smem_attn>>>(attn_mask, nullptr);

    gemm_tf32<<<gg, 256, SMEM_GEMM>>>(nullptr, wt + 3 * (size_t)Hdim * Hdim, bo, out, 3);
}

// round 17
// speedup vs baseline: 3.0717x; 2.0772x over previous
#include <cuda_runtime.h>
#include <cstdint>

#define Hdim 1024
#define Tlen 2048
#define Bb   2
#define NHh  16
#define HDd  64
#define NTOK (Bb * Tlen)

// Scratch (device globals: no allocation allowed in kernel_launch)
__device__ float g_Q[NTOK * Hdim];    // [B,NH,T,HD]
__device__ float g_K[NTOK * Hdim];    // [B,NH,T,HD]
__device__ float g_V[NTOK * Hdim];    // [B,NH,T,HD]
__device__ float g_ctx[NTOK * Hdim];  // [B*T, H] token-major
__device__ float g_Wt[4 * Hdim * Hdim]; // transposed weights [out][in]

// ===========================================================================
// helpers
// ===========================================================================
__device__ __forceinline__ uint32_t smem_u32(const void* p) {
    uint32_t a;
    asm("{ .reg .u64 t; cvta.to.shared.u64 t, %1; cvt.u32.u64 %0, t; }"
        : "=r"(a) : "l"(p));
    return a;
}
__device__ __forceinline__ void cp_async16(uint32_t saddr, const void* gptr) {
    asm volatile("cp.async.cg.shared.global [%0], [%1], 16;"
                 :: "r"(saddr), "l"(gptr) : "memory");
}
__device__ __forceinline__ uint32_t f2tf32(float f) {
    uint32_t u;
    asm("cvt.rna.tf32.f32 %0, %1;" : "=r"(u) : "f"(f));
    return u;
}
__device__ __forceinline__ void mma_tf32(float* d, const uint32_t* a,
                                         const uint32_t* b) {
    asm volatile(
        "mma.sync.aligned.m16n8k8.row.col.f32.tf32.tf32.f32 "
        "{%0,%1,%2,%3}, {%4,%5,%6,%7}, {%8,%9}, {%0,%1,%2,%3};"
        : "+f"(d[0]), "+f"(d[1]), "+f"(d[2]), "+f"(d[3])
        : "r"(a[0]), "r"(a[1]), "r"(a[2]), "r"(a[3]), "r"(b[0]), "r"(b[1]));
}

// ===========================================================================
// Weight transpose: Wt[n][k] = W[k][n], 1024x1024, 4 matrices
// ===========================================================================
__global__ void transpose4(const float* __restrict__ W0, const float* __restrict__ W1,
                           const float* __restrict__ W2, const float* __restrict__ W3)
{
    __shared__ float t[32][33];
    const float* in = (blockIdx.z == 0) ? W0 : (blockIdx.z == 1) ? W1 :
                      (blockIdx.z == 2) ? W2 : W3;
    float* out = g_Wt + (size_t)blockIdx.z * Hdim * Hdim;
    int x = blockIdx.x * 32 + threadIdx.x;
    int y = blockIdx.y * 32 + threadIdx.y;
#pragma unroll
    for (int i = 0; i < 32; i += 8)
        t[threadIdx.y + i][threadIdx.x] = in[(size_t)(y + i) * Hdim + x];
    __syncthreads();
    x = blockIdx.y * 32 + threadIdx.x;
    y = blockIdx.x * 32 + threadIdx.y;
#pragma unroll
    for (int i = 0; i < 32; i += 8)
        out[(size_t)(y + i) * Hdim + x] = t[threadIdx.x][threadIdx.y + i];
}

// ===========================================================================
// tf32 mma.sync GEMM (unchanged from R16): C[4096x1024] = X @ Wt^T + bias
// ===========================================================================
#define PITCH 36
#define STGF  (128 * PITCH)
#define SMEM_GEMM (4 * STGF * 4)

__global__ __launch_bounds__(256) void gemm_tf32(const float* __restrict__ Xin,
                                                 const float* __restrict__ Wt,
                                                 const float* __restrict__ bias,
                                                 float* __restrict__ outp,
                                                 int mode)
{
    extern __shared__ float smf[];
    const uint32_t sbase = smem_u32(smf);
    const int tid = threadIdx.x;
    const int wid = tid >> 5, lane = tid & 31;

    const float* X = (mode == 3) ? g_ctx : Xin;
    const int m0 = blockIdx.y << 7;
    const int n0 = blockIdx.x << 7;

    const int wm0 = (wid >> 2) << 6;
    const int wn0 = (wid & 3) << 5;

    const int lrow = tid >> 3;
    const int lc4 = tid & 7;

    float acc[4][4][4];
#pragma unroll
    for (int i = 0; i < 4; i++)
#pragma unroll
        for (int j = 0; j < 4; j++)
#pragma unroll
            for (int e = 0; e < 4; e++) acc[i][j][e] = 0.f;

    const int r4 = lane >> 2, c4 = lane & 3;

    {
        const uint32_t sA = sbase;
        const uint32_t sB = sbase + 2 * STGF * 4;
#pragma unroll
        for (int i = 0; i < 4; i++) {
            int rr = lrow + i * 32;
            uint32_t so = (uint32_t)(rr * PITCH + lc4 * 4) << 2;
            cp_async16(sA + so, X + (size_t)(m0 + rr) * Hdim + lc4 * 4);
            cp_async16(sB + so, Wt + (size_t)(n0 + rr) * Hdim + lc4 * 4);
        }
        asm volatile("cp.async.commit_group;" ::: "memory");
    }

    for (int c = 0; c < Hdim / 32; c++) {
        const int s = c & 1;
        if (c + 1 < Hdim / 32) {
            const int s1 = (c + 1) & 1;
            const int kc = (c + 1) * 32;
            const uint32_t sA = sbase + (uint32_t)(s1 * STGF) * 4;
            const uint32_t sB = sbase + (uint32_t)((2 + s1) * STGF) * 4;
#pragma unroll
            for (int i = 0; i < 4; i++) {
                int rr = lrow + i * 32;
                uint32_t so = (uint32_t)(rr * PITCH + lc4 * 4) << 2;
                cp_async16(sA + so, X + (size_t)(m0 + rr) * Hdim + kc + lc4 * 4);
                cp_async16(sB + so, Wt + (size_t)(n0 + rr) * Hdim + kc + lc4 * 4);
            }
            asm volatile("cp.async.commit_group;" ::: "memory");
            asm volatile("cp.async.wait_group 1;" ::: "memory");
        } else {
            asm volatile("cp.async.wait_group 0;" ::: "memory");
        }
        __syncthreads();

        const float* As = smf + s * STGF;
        const float* Bs = smf + (2 + s) * STGF;

#pragma unroll
        for (int ks = 0; ks < 4; ks++) {
            const int kb = ks * 8;
            uint32_t af[4][4], bf[4][2];
#pragma unroll
            for (int mi = 0; mi < 4; mi++) {
                const float* p = As + (wm0 + mi * 16 + r4) * PITCH + kb + c4;
                af[mi][0] = f2tf32(p[0]);
                af[mi][1] = f2tf32(p[8 * PITCH]);
                af[mi][2] = f2tf32(p[4]);
                af[mi][3] = f2tf32(p[8 * PITCH + 4]);
            }
#pragma unroll
            for (int nj = 0; nj < 4; nj++) {
                const float* p = Bs + (wn0 + nj * 8 + r4) * PITCH + kb + c4;
                bf[nj][0] = f2tf32(p[0]);
                bf[nj][1] = f2tf32(p[4]);
            }
#pragma unroll
            for (int mi = 0; mi < 4; mi++)
#pragma unroll
                for (int nj = 0; nj < 4; nj++)
                    mma_tf32(acc[mi][nj], af[mi], bf[nj]);
        }
        __syncthreads();
    }

    const float scale = (mode == 0) ? 0.125f : 1.0f;
    float* qkv = (mode == 0) ? g_Q : (mode == 1) ? g_K : (mode == 2) ? g_V : outp;
    const int c2 = (lane & 3) << 1;

#pragma unroll
    for (int mi = 0; mi < 4; mi++) {
        const int row0 = m0 + wm0 + mi * 16 + r4;
#pragma unroll
        for (int nj = 0; nj < 4; nj++) {
            const int col = n0 + wn0 + nj * 8 + c2;
            const float b0 = bias[col], b1 = bias[col + 1];
            if (mode == 3) {
                float2 v0 = make_float2(acc[mi][nj][0] + b0, acc[mi][nj][1] + b1);
                float2 v1 = make_float2(acc[mi][nj][2] + b0, acc[mi][nj][3] + b1);
                *(float2*)(qkv + (size_t)row0 * Hdim + col) = v0;
                *(float2*)(qkv + (size_t)(row0 + 8) * Hdim + col) = v1;
            } else {
                const int h = col >> 6, d = col & 63;
                float2 v0 = make_float2((acc[mi][nj][0] + b0) * scale,
                                        (acc[mi][nj][1] + b1) * scale);
                float2 v1 = make_float2((acc[mi][nj][2] + b0) * scale,
                                        (acc[mi][nj][3] + b1) * scale);
                {
                    int m = row0, bq = m >> 11, t = m & 2047;
                    *(float2*)(qkv + ((((size_t)bq * NHh + h) * Tlen + t) * HDd + d)) = v0;
                }
                {
                    int m = row0 + 8, bq = m >> 11, t = m & 2047;
                    *(float2*)(qkv + ((((size_t)bq * NHh + h) * Tlen + t) * HDd + d)) = v1;
                }
            }
        }
    }
}

// ===========================================================================
// Flash attention via mma.sync tf32.
//   CTA: 128 q-rows x one (b,h). 8 warps x 16 rows. K-tiles of 64 keys.
//   Q tf32 fragments held in registers for the whole kernel.
//   K/V double-buffered in smem, pre-converted to tf32 (V transposed [d][tok]).
//   S fragments in registers -> online softmax (quad shfl) -> P to smem (tf32)
//   -> PV mma accumulates O fragments in registers.
// ===========================================================================
#define APITCH 68
#define SMEM_ATTN ((128 * APITCH + 4 * 64 * APITCH) * 4 + 64 * 4)

__global__ __launch_bounds__(256) void attn_mma(const int* __restrict__ mask)
{
    extern __shared__ float sm[];
    float* Ps = sm;                                    // 128 x APITCH (Q stage fp32, then P tf32)
    uint32_t* Psu = (uint32_t*)Ps;
    uint32_t* Ksu = (uint32_t*)(Ps + 128 * APITCH);    // 2 stages 64 x APITCH (tf32)
    uint32_t* Vtu = Ksu + 2 * 64 * APITCH;             // 2 stages 64 x APITCH (tf32, [d][tok])
    int* mk = (int*)(Vtu + 2 * 64 * APITCH);           // 64

    const int tid = threadIdx.x;
    const int wid = tid >> 5, lane = tid & 31;
    const int r4 = lane >> 2, c4 = lane & 3;
    const int bh = blockIdx.y;
    const int b = bh >> 4, h = bh & 15;
    const int q0 = blockIdx.x << 7;
    const int wm = wid << 4;

    // ---- stage Q (fp32) into Ps, extract tf32 A fragments into registers ----
    const float* Qg = g_Q + ((size_t)bh * Tlen + q0) * HDd;
#pragma unroll
    for (int it = 0; it < 8; it++) {
        int idx = tid + it * 256;                      // 2048 float4 = 128x64
        int row = idx >> 4;
        int c = (idx & 15) << 2;
        *(float4*)(Ps + row * APITCH + c) = *(const float4*)(Qg + (size_t)row * HDd + c);
    }
    __syncthreads();
    uint32_t qa[8][4];
#pragma unroll
    for (int kb = 0; kb < 8; kb++) {
        const float* p = Ps + (wm + r4) * APITCH + kb * 8 + c4;
        qa[kb][0] = f2tf32(p[0]);
        qa[kb][1] = f2tf32(p[8 * APITCH]);
        qa[kb][2] = f2tf32(p[4]);
        qa[kb][3] = f2tf32(p[8 * APITCH + 4]);
    }

    // ---- prefetch K/V tile 0 into registers ----
    const float* Kg0 = g_K + (size_t)bh * Tlen * HDd;
    const float* Vg0 = g_V + (size_t)bh * Tlen * HDd;
    const int prow = tid >> 2, pc0 = (tid & 3) << 4;   // 64 rows x 4 float4 strips
    float4 kr[4], vr[4];
    {
        const float* Kg = Kg0 + (size_t)prow * HDd + pc0;
        const float* Vg = Vg0 + (size_t)prow * HDd + pc0;
#pragma unroll
        for (int j = 0; j < 4; j++) {
            kr[j] = *(const float4*)(Kg + j * 4);
            vr[j] = *(const float4*)(Vg + j * 4);
        }
    }

    float o[8][4];
#pragma unroll
    for (int nj = 0; nj < 8; nj++)
#pragma unroll
        for (int e = 0; e < 4; e++) o[nj][e] = 0.f;
    float mrow0 = -1e30f, mrow1 = -1e30f, l0 = 0.f, l1 = 0.f;

    for (int kt = 0; kt < Tlen / 64; kt++) {
        const int s = kt & 1;
        uint32_t* Kst = Ksu + s * 64 * APITCH;
        uint32_t* Vst = Vtu + s * 64 * APITCH;

        // cvt + store K natural rows, V transposed [d][tok], both tf32 bits
#pragma unroll
        for (int j = 0; j < 4; j++) {
            int d0 = pc0 + j * 4;
            Kst[prow * APITCH + d0 + 0] = f2tf32(kr[j].x);
            Kst[prow * APITCH + d0 + 1] = f2tf32(kr[j].y);
            Kst[prow * APITCH + d0 + 2] = f2tf32(kr[j].z);
            Kst[prow * APITCH + d0 + 3] = f2tf32(kr[j].w);
            Vst[(d0 + 0) * APITCH + prow] = f2tf32(vr[j].x);
            Vst[(d0 + 1) * APITCH + prow] = f2tf32(vr[j].y);
            Vst[(d0 + 2) * APITCH + prow] = f2tf32(vr[j].z);
            Vst[(d0 + 3) * APITCH + prow] = f2tf32(vr[j].w);
        }
        if (tid < 64) mk[tid] = mask[b * Tlen + kt * 64 + tid];
        __syncthreads();

        // prefetch next tile (latency hidden behind this tile's compute)
        if (kt + 1 < Tlen / 64) {
            const float* Kg = Kg0 + ((size_t)(kt + 1) * 64 + prow) * HDd + pc0;
            const float* Vg = Vg0 + ((size_t)(kt + 1) * 64 + prow) * HDd + pc0;
#pragma unroll
            for (int j = 0; j < 4; j++) {
                kr[j] = *(const float4*)(Kg + j * 4);
                vr[j] = *(const float4*)(Vg + j * 4);
            }
        }

        // ---- S = Q K^T (m16 x n64 per warp, fragments in registers) ----
        float sfr[8][4];
#pragma unroll
        for (int nj = 0; nj < 8; nj++)
#pragma unroll
            for (int e = 0; e < 4; e++) sfr[nj][e] = 0.f;
#pragma unroll
        for (int kb = 0; kb < 8; kb++) {
            uint32_t bf[8][2];
#pragma unroll
            for (int nj = 0; nj < 8; nj++) {
                const uint32_t* p = Kst + (nj * 8 + r4) * APITCH + kb * 8 + c4;
                bf[nj][0] = p[0];
                bf[nj][1] = p[4];
            }
#pragma unroll
            for (int nj = 0; nj < 8; nj++)
                mma_tf32(sfr[nj], qa[kb], bf[nj]);
        }

        // ---- mask + online softmax (rows r4 and r4+8 of warp tile) ----
        float mx0 = -1e30f, mx1 = -1e30f;
#pragma unroll
        for (int nj = 0; nj < 8; nj++) {
            int col = nj * 8 + (c4 << 1);
            if (!mk[col])     { sfr[nj][0] = -1e30f; sfr[nj][2] = -1e30f; }
            if (!mk[col + 1]) { sfr[nj][1] = -1e30f; sfr[nj][3] = -1e30f; }
            mx0 = fmaxf(mx0, fmaxf(sfr[nj][0], sfr[nj][1]));
            mx1 = fmaxf(mx1, fmaxf(sfr[nj][2], sfr[nj][3]));
        }
        mx0 = fmaxf(mx0, __shfl_xor_sync(0xffffffffu, mx0, 1));
        mx0 = fmaxf(mx0, __shfl_xor_sync(0xffffffffu, mx0, 2));
        mx1 = fmaxf(mx1, __shfl_xor_sync(0xffffffffu, mx1, 1));
        mx1 = fmaxf(mx1, __shfl_xor_sync(0xffffffffu, mx1, 2));

        float mn0 = fmaxf(mrow0, mx0), mn1 = fmaxf(mrow1, mx1);
        float a0 = __expf(mrow0 - mn0), a1 = __expf(mrow1 - mn1);
        mrow0 = mn0; mrow1 = mn1;

        float sum0 = 0.f, sum1 = 0.f;
#pragma unroll
        for (int nj = 0; nj < 8; nj++) {
            float p00 = __expf(sfr[nj][0] - mn0);
            float p01 = __expf(sfr[nj][1] - mn0);
            float p10 = __expf(sfr[nj][2] - mn1);
            float p11 = __expf(sfr[nj][3] - mn1);
            sum0 += p00 + p01;
            sum1 += p10 + p11;
            int col = nj * 8 + (c4 << 1);
            uint32_t* pp = Psu + (wm + r4) * APITCH + col;
            pp[0] = f2tf32(p00); pp[1] = f2tf32(p01);
            uint32_t* pq = Psu + (wm + r4 + 8) * APITCH + col;
            pq[0] = f2tf32(p10); pq[1] = f2tf32(p11);
        }
        sum0 += __shfl_xor_sync(0xffffffffu, sum0, 1);
        sum0 += __shfl_xor_sync(0xffffffffu, sum0, 2);
        sum1 += __shfl_xor_sync(0xffffffffu, sum1, 1);
        sum1 += __shfl_xor_sync(0xffffffffu, sum1, 2);
        l0 = l0 * a0 + sum0;
        l1 = l1 * a1 + sum1;

#pragma unroll
        for (int nj = 0; nj < 8; nj++) {
            o[nj][0] *= a0; o[nj][1] *= a0;
            o[nj][2] *= a1; o[nj][3] *= a1;
        }
        __syncthreads();   // P tile + V stage fully written before PV

        // ---- O += P V ----
#pragma unroll
        for (int kb = 0; kb < 8; kb++) {
            uint32_t pa[4];
            const uint32_t* p = Psu + (wm + r4) * APITCH + kb * 8 + c4;
            pa[0] = p[0];
            pa[1] = p[8 * APITCH];
            pa[2] = p[4];
            pa[3] = p[8 * APITCH + 4];
            uint32_t bf[8][2];
#pragma unroll
            for (int nj = 0; nj < 8; nj++) {
                const uint32_t* q = Vst + (nj * 8 + r4) * APITCH + kb * 8 + c4;
                bf[nj][0] = q[0];
                bf[nj][1] = q[4];
            }
#pragma unroll
            for (int nj = 0; nj < 8; nj++)
                mma_tf32(o[nj], pa, bf[nj]);
        }
    }

    // ---- epilogue: normalize and write ctx ----
    float i0 = 1.f / l0, i1 = 1.f / l1;
    const int row0 = q0 + wm + r4;
    float* og = g_ctx + ((size_t)b * Tlen) * Hdim + (size_t)h * HDd;
#pragma unroll
    for (int nj = 0; nj < 8; nj++) {
        int col = nj * 8 + (c4 << 1);
        *(float2*)(og + (size_t)row0 * Hdim + col) =
            make_float2(o[nj][0] * i0, o[nj][1] * i0);
        *(float2*)(og + (size_t)(row0 + 8) * Hdim + col) =
            make_float2(o[nj][2] * i1, o[nj][3] * i1);
    }
}

// ---------------------------------------------------------------------------
extern "C" void kernel_launch(void* const* d_in, const int* in_sizes, int n_in,
                              void* d_out, int out_size)
{
    const float* x  = (const float*)d_in[0];
    const int* attn_mask = (const int*)d_in[1];
    const float* Wq = (const float*)d_in[2];
    const float* bq = (const float*)d_in[3];
    const float* Wk = (const float*)d_in[4];
    const float* bk = (const float*)d_in[5];
    const float* Wv = (const float*)d_in[6];
    const float* bv = (const float*)d_in[7];
    const float* Wo = (const float*)d_in[8];
    const float* bo = (const float*)d_in[9];
    float* out = (float*)d_out;

    cudaFuncSetAttribute(gemm_tf32, cudaFuncAttributeMaxDynamicSharedMemorySize,
                         SMEM_GEMM);
    cudaFuncSetAttribute(attn_mma, cudaFuncAttributeMaxDynamicSharedMemorySize,
                         SMEM_ATTN);

    transpose4<<<dim3(32, 32, 4), dim3(32, 8)>>>(Wq, Wk, Wv, Wo);

    float* wt = nullptr;
    cudaGetSymbolAddress((void**)&wt, g_Wt);

    dim3 gg(Hdim / 128, NTOK / 128);  // (8, 32)
    gemm_tf32<<<gg, 256, SMEM_GEMM>>>(x, wt + 0 * (size_t)Hdim * Hdim, bq, nullptr, 0);
    gemm_tf32<<<gg, 256, SMEM_GEMM>>>(x, wt + 1 * (size_t)Hdim * Hdim, bk, nullptr, 1);
    gemm_tf32<<<gg, 256, SMEM_GEMM>>>(x, wt + 2 * (size_t)Hdim * Hdim, bv, nullptr, 2);

    dim3 ga(Tlen / 128, Bb * NHh);    // (16, 32)
    attn_mma<<<ga, 256, SMEM_ATTN>>>(attn_mask);

    gemm_tf32<<<gg, 256, SMEM_GEMM>>>(nullptr, wt + 3 * (size_t)Hdim * Hdim, bo, out, 3);
}